// round 2
// baseline (speedup 1.0000x reference)
#include <cuda_runtime.h>
#include <math.h>
#include <limits.h>

#define N_USER 20000
#define N_ITEM 20000
#define NN     40000
#define DD     128
#define HH     4
#define LLAYERS 2
#define MMEM   8
#define TREL   5
#define E_UI_C 40000
#define E_T_C  16000
#define FEPS   1e-5f

// ---------------- device scratch (no cudaMalloc allowed) ----------------
__device__ float g_emb[3L * NN * DD];                 // all_emb[0..2]
__device__ float g_fs[(long)N_USER * HH * DD];        // fc(src)
__device__ float g_fd[(long)N_USER * HH * DD];        // fc(dst)
__device__ float g_rst[(long)N_USER * HH * DD];       // GAT aggregation
__device__ float g_trans[(long)NN * DD];
__device__ float g_el[N_USER * HH];
__device__ float g_er[N_USER * HH];
__device__ int   g_emax[N_USER * HH];
__device__ float g_denom[N_USER * HH];
__device__ float g_e[E_UI_C * HH];
__device__ float g_ex[E_UI_C * HH];
__device__ float g_agg[(long)NN * DD];
__device__ float g_cnt[NN];
__device__ float g_coef[(long)TREL * E_T_C * MMEM];
__device__ float g_ncoef[(long)NN * MMEM];
__device__ float g_tmp[(long)TREL * E_T_C * MMEM * DD];   // 81.92M floats, reused for node path

// ---------------- helpers ----------------
__device__ __forceinline__ float lrelu(float x) { return x > 0.f ? x : 0.2f * x; }
__device__ __forceinline__ float eluf(float x)  { return x > 0.f ? x : expm1f(x); }
__device__ __forceinline__ int   encf(float f)  { int i = __float_as_int(f); return i >= 0 ? i : (i ^ 0x7FFFFFFF); }
__device__ __forceinline__ float decf(int i)    { return __int_as_float(i >= 0 ? i : (i ^ 0x7FFFFFFF)); }

__device__ __forceinline__ float blockSum128(float v, float* sbuf) {
    #pragma unroll
    for (int o = 16; o; o >>= 1) v += __shfl_xor_sync(0xffffffffu, v, o);
    int w = threadIdx.x >> 5;
    if ((threadIdx.x & 31) == 0) sbuf[w] = v;
    __syncthreads();
    float r = sbuf[0] + sbuf[1] + sbuf[2] + sbuf[3];
    __syncthreads();
    return r;
}

// ---------------- generic SIMT GEMM: C = act(A[M,K] @ B[N,K]^T (+bias)) ----------------
// optional row-gather on A, grid.z batching over B/C/idx.
#define BM 128
#define BN 128
#define BK 16

template<int ACT>  // 0: none, 1: elu(x + bias[col])
__global__ void __launch_bounds__(256) gemm_bt(
    const float* __restrict__ A, int lda,
    const float* __restrict__ B, long strideB,
    float* __restrict__ C, int ldc, long strideC,
    const float* __restrict__ bias,
    const int* __restrict__ gidx, int strideIdx,
    int Mm, int Nn, int Kk)
{
    int z = blockIdx.z;
    B += (long)z * strideB;
    C += (long)z * strideC;
    if (gidx) gidx += (long)z * strideIdx;

    __shared__ float As[BK][BM + 4];
    __shared__ float Bs[BK][BN + 4];

    int tid = threadIdx.x;
    int tx = tid & 15, ty = tid >> 4;
    int row0 = blockIdx.y * BM;
    int col0 = blockIdx.x * BN;

    float acc[8][8];
    #pragma unroll
    for (int i = 0; i < 8; i++)
        #pragma unroll
        for (int j = 0; j < 8; j++) acc[i][j] = 0.f;

    for (int k0 = 0; k0 < Kk; k0 += BK) {
        // load A tile (with optional gather), transposed into As[k][m]
        #pragma unroll
        for (int i = 0; i < 2; i++) {
            int lin = tid + i * 256;     // 512 float4 loads total
            int r = lin >> 2, c4 = lin & 3;
            int gr = row0 + r;
            float4 v = make_float4(0.f, 0.f, 0.f, 0.f);
            if (gr < Mm) {
                int ar = gidx ? gidx[gr] : gr;
                v = *reinterpret_cast<const float4*>(&A[(long)ar * lda + k0 + c4 * 4]);
            }
            As[c4 * 4 + 0][r] = v.x; As[c4 * 4 + 1][r] = v.y;
            As[c4 * 4 + 2][r] = v.z; As[c4 * 4 + 3][r] = v.w;
        }
        // load B tile (N always multiple of 128 here)
        #pragma unroll
        for (int i = 0; i < 2; i++) {
            int lin = tid + i * 256;
            int r = lin >> 2, c4 = lin & 3;
            float4 v = *reinterpret_cast<const float4*>(&B[(long)(col0 + r) * Kk + k0 + c4 * 4]);
            Bs[c4 * 4 + 0][r] = v.x; Bs[c4 * 4 + 1][r] = v.y;
            Bs[c4 * 4 + 2][r] = v.z; Bs[c4 * 4 + 3][r] = v.w;
        }
        __syncthreads();
        #pragma unroll
        for (int k = 0; k < BK; k++) {
            float af[8], bf[8];
            #pragma unroll
            for (int i = 0; i < 8; i++) af[i] = As[k][ty * 8 + i];
            #pragma unroll
            for (int j = 0; j < 8; j++) bf[j] = Bs[k][tx * 8 + j];
            #pragma unroll
            for (int i = 0; i < 8; i++)
                #pragma unroll
                for (int j = 0; j < 8; j++) acc[i][j] = fmaf(af[i], bf[j], acc[i][j]);
        }
        __syncthreads();
    }

    #pragma unroll
    for (int i = 0; i < 8; i++) {
        int r = row0 + ty * 8 + i;
        if (r >= Mm) continue;
        #pragma unroll
        for (int j = 0; j < 8; j++) {
            int c = col0 + tx * 8 + j;
            float v = acc[i][j];
            if (ACT == 1) { v += bias[c]; v = eluf(v); }
            C[(long)r * ldc + c] = v;
        }
    }
}

// ---------------- small kernels ----------------
__global__ void copy_emb0(const float* __restrict__ e) {
    long i = (long)blockIdx.x * blockDim.x + threadIdx.x;
    if (i < (long)NN * DD) g_emb[i] = e[i];
}

__global__ void gat_init() {
    long i = (long)blockIdx.x * blockDim.x + threadIdx.x;
    if (i < (long)N_USER * HH * DD) g_rst[i] = 0.f;
    if (i < N_USER * HH) { g_emax[i] = INT_MIN; g_denom[i] = 0.f; }
}

__global__ void mem_init() {
    long i = (long)blockIdx.x * blockDim.x + threadIdx.x;
    if (i < (long)NN * DD) g_agg[i] = 0.f;
    if (i < NN) g_cnt[i] = 0.f;
}

// el/er: dot of fc features with attention vector per head
__global__ void eler_kernel(const float* __restrict__ f, const float* __restrict__ attn,
                            float* __restrict__ out, int n) {
    int gwarp = (blockIdx.x * blockDim.x + threadIdx.x) >> 5;
    int lane = threadIdx.x & 31;
    if (gwarp >= n) return;
    const float* fr = f + (long)gwarp * (HH * DD);
    float p = 0.f;
    #pragma unroll
    for (int j = 0; j < 16; j++) p += fr[lane * 16 + j] * attn[lane * 16 + j];
    p += __shfl_xor_sync(0xffffffffu, p, 1);
    p += __shfl_xor_sync(0xffffffffu, p, 2);
    p += __shfl_xor_sync(0xffffffffu, p, 4);
    if ((lane & 7) == 0) out[gwarp * HH + (lane >> 3)] = p;
}

__global__ void gat_edge1(const int* __restrict__ s, const int* __restrict__ d, int E) {
    int i = blockIdx.x * blockDim.x + threadIdx.x;
    if (i >= E) return;
    int si = s[i], di = d[i];
    #pragma unroll
    for (int h = 0; h < HH; h++) {
        float e = lrelu(g_el[si * HH + h] + g_er[di * HH + h]);
        g_e[i * HH + h] = e;
        atomicMax(&g_emax[di * HH + h], encf(e));
    }
}

__global__ void gat_edge2(const int* __restrict__ d, int E) {
    int i = blockIdx.x * blockDim.x + threadIdx.x;
    if (i >= E) return;
    int di = d[i];
    #pragma unroll
    for (int h = 0; h < HH; h++) {
        float v = expf(g_e[i * HH + h] - decf(g_emax[di * HH + h]));
        g_ex[i * HH + h] = v;
        atomicAdd(&g_denom[di * HH + h], v);
    }
}

__global__ void gat_edge3(const int* __restrict__ s, const int* __restrict__ d) {
    int e = blockIdx.x;            // one edge per block, 512 threads = H*D
    int tid = threadIdx.x;
    int si = s[e], di = d[e];
    int h = tid >> 7;
    float a = g_ex[e * HH + h] / g_denom[di * HH + h];
    atomicAdd(&g_rst[(long)di * 512 + tid], a * g_fs[(long)si * 512 + tid]);
}

__global__ void elu_bias_kernel(const float* __restrict__ bias, long n) {
    long i = (long)blockIdx.x * blockDim.x + threadIdx.x;
    if (i >= n) return;
    g_rst[i] = eluf(g_rst[i] + bias[i & 511]);
}

// coef = leaky(feat[idx] . Wc[m] + bc[m]); one warp per edge/node
__global__ void coef_kernel(const float* __restrict__ feat,
                            const int* __restrict__ idx, int idxStride,
                            const float* __restrict__ Wc, int WcStride,
                            const float* __restrict__ bc, int bcStride,
                            float* __restrict__ out, int count) {
    int z = blockIdx.y;
    __shared__ float sW[MMEM * DD];
    __shared__ float sb[MMEM];
    const float* W = Wc + (long)z * WcStride;
    for (int i = threadIdx.x; i < MMEM * DD; i += 256) sW[i] = W[i];
    if (threadIdx.x < MMEM) sb[threadIdx.x] = bc[z * bcStride + threadIdx.x];
    __syncthreads();
    int warp = threadIdx.x >> 5, lane = threadIdx.x & 31;
    int e = blockIdx.x * 8 + warp;
    if (e >= count) return;
    int node = idx ? idx[(long)z * idxStride + e] : e;
    const float* f = feat + (long)node * DD;
    float fv[4];
    #pragma unroll
    for (int j = 0; j < 4; j++) fv[j] = f[lane * 4 + j];
    #pragma unroll
    for (int m = 0; m < MMEM; m++) {
        float p = 0.f;
        #pragma unroll
        for (int j = 0; j < 4; j++) p += fv[j] * sW[m * DD + lane * 4 + j];
        #pragma unroll
        for (int o = 16; o; o >>= 1) p += __shfl_xor_sync(0xffffffffu, p, o);
        if (lane == 0) out[((long)z * count + e) * MMEM + m] = lrelu(p + sb[m]);
    }
}

// msg[e] = sum_m coef[e,m]*tmp[e,m,:]; scatter-add into agg/cnt
__global__ void rel_reduce(const int* __restrict__ edst) {
    int t = blockIdx.y, e = blockIdx.x, tid = threadIdx.x;
    long ei = (long)t * E_T_C + e;
    int dd = edst[ei];
    __shared__ float c[MMEM];
    if (tid < MMEM) c[tid] = g_coef[ei * MMEM + tid];
    __syncthreads();
    const float* tp = g_tmp + ei * (MMEM * DD);
    float s = 0.f;
    #pragma unroll
    for (int m = 0; m < MMEM; m++) s += c[m] * tp[m * DD + tid];
    atomicAdd(&g_agg[(long)dd * DD + tid], s);
    if (tid == 0) atomicAdd(&g_cnt[dd], 1.0f);
}

// per-node: LN(agg/cnt)+h_bias + node-memory + leaky, + trans -> next emb
__global__ void mem_finalize(const float* __restrict__ lnw, const float* __restrict__ lnb,
                             const float* __restrict__ hb, float* __restrict__ out) {
    int n = blockIdx.x, tid = threadIdx.x;
    __shared__ float sbuf[4];
    __shared__ float snc[MMEM];
    if (tid < MMEM) snc[tid] = g_ncoef[(long)n * MMEM + tid];
    float a = g_agg[(long)n * DD + tid] / fmaxf(g_cnt[n], 1.0f);
    float mu = blockSum128(a, sbuf) * (1.0f / 128.0f);
    float dv = a - mu;
    float var = blockSum128(dv * dv, sbuf) * (1.0f / 128.0f);
    float rep = dv * rsqrtf(var + FEPS) * lnw[tid] + lnb[tid] + hb[tid];
    const float* tp = g_tmp + (long)n * (MMEM * DD);
    float s = 0.f;
    #pragma unroll
    for (int m = 0; m < MMEM; m++) s += snc[m] * tp[m * DD + tid];
    rep = lrelu(rep + s);
    out[(long)n * DD + tid] = rep + g_trans[(long)n * DD + tid];
}

__global__ void final_ln_kernel(const float* __restrict__ w, const float* __restrict__ b,
                                float* __restrict__ out) {
    int n = blockIdx.x, tid = threadIdx.x;
    __shared__ float sbuf[4];
    float v0 = g_emb[(long)n * DD + tid];
    float v1 = g_emb[(long)NN * DD + (long)n * DD + tid];
    float v2 = g_emb[2L * NN * DD + (long)n * DD + tid];
    float mu = blockSum128(v0 + v1 + v2, sbuf) * (1.0f / 384.0f);
    float d0 = v0 - mu, d1 = v1 - mu, d2 = v2 - mu;
    float var = blockSum128(d0 * d0 + d1 * d1 + d2 * d2, sbuf) * (1.0f / 384.0f);
    float r = rsqrtf(var + FEPS);
    long base = (long)n * 384;
    out[base + tid]       = d0 * r * w[tid]       + b[tid];
    out[base + 128 + tid] = d1 * r * w[128 + tid] + b[128 + tid];
    out[base + 256 + tid] = d2 * r * w[256 + tid] + b[256 + tid];
}

// ---------------- host orchestration ----------------
extern "C" void kernel_launch(void* const* d_in, const int* in_sizes, int n_in,
                              void* d_out, int out_size) {
    const float* embedding   = (const float*)d_in[0];
    const float* gat_fc_W    = (const float*)d_in[1];
    const float* gat_attn_l  = (const float*)d_in[2];
    const float* gat_attn_r  = (const float*)d_in[3];
    const float* gat_bias    = (const float*)d_in[4];
    const float* proj_W      = (const float*)d_in[5];
    const float* proj_b      = (const float*)d_in[6];
    const float* mem_rel_Wc  = (const float*)d_in[7];
    const float* mem_rel_bc  = (const float*)d_in[8];
    const float* mem_rel_Ww  = (const float*)d_in[9];
    const float* mem_node_Wc = (const float*)d_in[10];
    const float* mem_node_bc = (const float*)d_in[11];
    const float* mem_node_Ww = (const float*)d_in[12];
    const float* mem_h_bias  = (const float*)d_in[13];
    const float* mem_ln_w    = (const float*)d_in[14];
    const float* mem_ln_b    = (const float*)d_in[15];
    const float* final_ln_w  = (const float*)d_in[16];
    const float* final_ln_b  = (const float*)d_in[17];
    const int*   src_u       = (const int*)d_in[18];
    const int*   dst_i       = (const int*)d_in[19];
    const int*   edge_src    = (const int*)d_in[20];
    const int*   edge_dst    = (const int*)d_in[21];

    float *emb, *fs, *fd, *rst, *trans, *el, *er, *tmp;
    cudaGetSymbolAddress((void**)&emb,   g_emb);
    cudaGetSymbolAddress((void**)&fs,    g_fs);
    cudaGetSymbolAddress((void**)&fd,    g_fd);
    cudaGetSymbolAddress((void**)&rst,   g_rst);
    cudaGetSymbolAddress((void**)&trans, g_trans);
    cudaGetSymbolAddress((void**)&el,    g_el);
    cudaGetSymbolAddress((void**)&er,    g_er);
    cudaGetSymbolAddress((void**)&tmp,   g_tmp);
    float* coefp;  cudaGetSymbolAddress((void**)&coefp,  g_coef);
    float* ncoefp; cudaGetSymbolAddress((void**)&ncoefp, g_ncoef);

    copy_emb0<<<(NN * DD + 255) / 256, 256>>>(embedding);

    for (int l = 0; l < LLAYERS; l++) {
        const float* fl = emb + (long)l * NN * DD;
        float* flout = emb + (long)(l + 1) * NN * DD;

        // -------- two GAT directions --------
        for (int s = 0; s < 2; s++) {
            const float* Asrc = (s == 0) ? fl + (long)N_USER * DD : fl;  // h_src
            const float* Adst = (s == 0) ? fl : fl + (long)N_USER * DD;  // h_dst
            const int* sidx = (s == 0) ? dst_i : src_u;
            const int* didx = (s == 0) ? src_u : dst_i;
            const float* W  = gat_fc_W  + ((long)l * 2 + s) * 512 * 128;
            const float* al = gat_attn_l + ((long)l * 2 + s) * 512;
            const float* ar = gat_attn_r + ((long)l * 2 + s) * 512;
            const float* gb = gat_bias   + ((long)l * 2 + s) * 512;
            const float* pW = proj_W     + ((long)l * 2 + s) * 128 * 512;
            const float* pb = proj_b     + ((long)l * 2 + s) * 128;

            dim3 gfc(4, (N_USER + BM - 1) / BM, 1);
            gemm_bt<0><<<gfc, 256>>>(Asrc, DD, W, 0, fs, 512, 0, nullptr, nullptr, 0,
                                     N_USER, 512, DD);
            gemm_bt<0><<<gfc, 256>>>(Adst, DD, W, 0, fd, 512, 0, nullptr, nullptr, 0,
                                     N_USER, 512, DD);
            eler_kernel<<<(N_USER + 7) / 8, 256>>>(fs, al, el, N_USER);
            eler_kernel<<<(N_USER + 7) / 8, 256>>>(fd, ar, er, N_USER);
            gat_init<<<(N_USER * 512 + 255) / 256, 256>>>();
            gat_edge1<<<(E_UI_C + 255) / 256, 256>>>(sidx, didx, E_UI_C);
            gat_edge2<<<(E_UI_C + 255) / 256, 256>>>(didx, E_UI_C);
            gat_edge3<<<E_UI_C, 512>>>(sidx, didx);
            elu_bias_kernel<<<(N_USER * 512 + 255) / 256, 256>>>(gb, (long)N_USER * 512);
            // projection + elu -> trans slice
            float* Cp = trans + (long)s * N_USER * DD;
            dim3 gp(1, (N_USER + BM - 1) / BM, 1);
            gemm_bt<1><<<gp, 256>>>(rst, 512, pW, 0, Cp, DD, 0, pb, nullptr, 0,
                                    N_USER, DD, 512);
        }

        // -------- memory layer (reads fl, independent of trans until finalize) --------
        mem_init<<<(NN * DD + 255) / 256, 256>>>();
        {
            dim3 gc((E_T_C + 7) / 8, TREL);
            coef_kernel<<<gc, 256>>>(fl, edge_dst, E_T_C,
                                     mem_rel_Wc + (long)l * TREL * MMEM * DD, MMEM * DD,
                                     mem_rel_bc + (long)l * TREL * MMEM, MMEM,
                                     coefp, E_T_C);
            dim3 gr(8, E_T_C / BM, TREL);   // N=1024, M=16000, z=t
            gemm_bt<0><<<gr, 256>>>(fl, DD,
                                    mem_rel_Ww + (long)l * TREL * MMEM * DD * DD,
                                    (long)MMEM * DD * DD,
                                    tmp, MMEM * DD, (long)E_T_C * MMEM * DD,
                                    nullptr, edge_src, E_T_C,
                                    E_T_C, MMEM * DD, DD);
            dim3 gs(E_T_C, TREL);
            rel_reduce<<<gs, 128>>>(edge_dst);

            dim3 gnc((NN + 7) / 8, 1);
            coef_kernel<<<gnc, 256>>>(fl, nullptr, 0,
                                      mem_node_Wc + (long)l * MMEM * DD, 0,
                                      mem_node_bc + (long)l * MMEM, 0,
                                      ncoefp, NN);
            dim3 gn(8, (NN + BM - 1) / BM, 1);
            gemm_bt<0><<<gn, 256>>>(fl, DD,
                                    mem_node_Ww + (long)l * MMEM * DD * DD, 0,
                                    tmp, MMEM * DD, 0,
                                    nullptr, nullptr, 0,
                                    NN, MMEM * DD, DD);
            mem_finalize<<<NN, 128>>>(mem_ln_w + l * DD, mem_ln_b + l * DD,
                                      mem_h_bias + l * DD, flout);
        }
    }

    final_ln_kernel<<<NN, 128>>>(final_ln_w, final_ln_b, (float*)d_out);
}

// round 7
// speedup vs baseline: 1.2221x; 1.2221x over previous
#include <cuda_runtime.h>
#include <math.h>
#include <limits.h>

#define N_USER 20000
#define N_ITEM 20000
#define NN     40000
#define DD     128
#define HH     4
#define LLAYERS 2
#define MMEM   8
#define TREL   5
#define E_UI_C 40000
#define E_T_C  16000
#define FEPS   1e-5f

#define BK 16
#define BN 128

// ---------------- device scratch (no cudaMalloc allowed) ----------------
__device__ float g_emb[2L * NN * DD];                 // layers 1,2 (layer0 = input)
__device__ float g_fc[(long)NN * HH * DD];            // combined fc output (users;items)
__device__ float g_rst[(long)N_USER * HH * DD];       // GAT aggregation
__device__ float g_trans[(long)NN * DD];
__device__ float g_el[N_USER * HH];
__device__ float g_er[N_USER * HH];
__device__ int   g_emax[N_USER * HH];
__device__ float g_denom[N_USER * HH];
__device__ float g_e[E_UI_C * HH];
__device__ float g_ex[E_UI_C * HH];
__device__ float g_agg[(long)NN * DD];
__device__ float g_cnt[NN];
__device__ float g_coef[(long)TREL * E_T_C * MMEM];
__device__ float g_ncoef[(long)NN * MMEM];
__device__ float g_tmp[(long)TREL * E_T_C * MMEM * DD];   // reused for node path

// ---------------- helpers ----------------
__device__ __forceinline__ float lrelu(float x) { return x > 0.f ? x : 0.2f * x; }
__device__ __forceinline__ float eluf(float x)  { return x > 0.f ? x : expm1f(x); }
__device__ __forceinline__ int   encf(float f)  { int i = __float_as_int(f); return i >= 0 ? i : (i ^ 0x7FFFFFFF); }
__device__ __forceinline__ float decf(int i)    { return __int_as_float(i >= 0 ? i : (i ^ 0x7FFFFFFF)); }

// ---------------- generic double-buffered SIMT GEMM ----------------
// C = act(A[M,K] @ B[N,K]^T), optional row-gather on A, z-batching over B/C/idx.
// ACT: 0 plain, 1 elu(x + colBias), 2 plain + fused attention dot (per 128-col head).
// ATR: 1 -> apply elu(a + aBias[k]) to A elements during load.
template<int TM, int ACT, int ATR, int GATHER>
__global__ void __launch_bounds__(256, 2) gemm_bt(
    const float* __restrict__ A, int lda,
    const float* __restrict__ B, long strideB,
    float* __restrict__ C, int ldc, long strideC,
    const float* __restrict__ colBias,
    const float* __restrict__ aBias,
    const float* __restrict__ attnLo, float* __restrict__ outLo,
    const float* __restrict__ attnHi, float* __restrict__ outHi,
    const int* __restrict__ gidx, int strideIdx,
    int Mm, int Nn, int Kk)
{
    constexpr int BMt = TM * 16;
    constexpr int NA  = TM / 4;      // A float4 loads per thread per stage

    int z = blockIdx.z;
    B += (long)z * strideB;
    C += (long)z * strideC;
    const int* gptr = GATHER ? (gidx + (long)z * strideIdx) : nullptr;

    __shared__ float As[2][BK][BMt + 4];
    __shared__ float Bs[2][BK][BN + 4];

    int tid = threadIdx.x;
    int tx = tid & 15, ty = tid >> 4;
    int row0 = blockIdx.y * BMt;
    int col0 = blockIdx.x * BN;

    float acc[TM][8];
    #pragma unroll
    for (int i = 0; i < TM; i++)
        #pragma unroll
        for (int j = 0; j < 8; j++) acc[i][j] = 0.f;

    float4 aR[NA], bR[2];

    auto loadG = [&](int k0) {
        #pragma unroll
        for (int i = 0; i < NA; i++) {
            int lin = tid + i * 256;
            int r = lin >> 2, c4 = lin & 3;
            int gr = row0 + r;
            float4 v = make_float4(0.f, 0.f, 0.f, 0.f);
            if (gr < Mm) {
                long ar = GATHER ? (long)gptr[gr] : (long)gr;
                v = *reinterpret_cast<const float4*>(&A[ar * lda + k0 + c4 * 4]);
                if (ATR) {
                    float4 b4 = *reinterpret_cast<const float4*>(&aBias[k0 + c4 * 4]);
                    v.x = eluf(v.x + b4.x); v.y = eluf(v.y + b4.y);
                    v.z = eluf(v.z + b4.z); v.w = eluf(v.w + b4.w);
                }
            }
            aR[i] = v;
        }
        #pragma unroll
        for (int i = 0; i < 2; i++) {
            int lin = tid + i * 256;
            int r = lin >> 2, c4 = lin & 3;
            bR[i] = *reinterpret_cast<const float4*>(&B[(long)(col0 + r) * Kk + k0 + c4 * 4]);
        }
    };
    auto storeS = [&](int buf) {
        #pragma unroll
        for (int i = 0; i < NA; i++) {
            int lin = tid + i * 256;
            int r = lin >> 2, c4 = lin & 3;
            As[buf][c4 * 4 + 0][r] = aR[i].x; As[buf][c4 * 4 + 1][r] = aR[i].y;
            As[buf][c4 * 4 + 2][r] = aR[i].z; As[buf][c4 * 4 + 3][r] = aR[i].w;
        }
        #pragma unroll
        for (int i = 0; i < 2; i++) {
            int lin = tid + i * 256;
            int r = lin >> 2, c4 = lin & 3;
            Bs[buf][c4 * 4 + 0][r] = bR[i].x; Bs[buf][c4 * 4 + 1][r] = bR[i].y;
            Bs[buf][c4 * 4 + 2][r] = bR[i].z; Bs[buf][c4 * 4 + 3][r] = bR[i].w;
        }
    };

    int nk = Kk / BK;
    loadG(0); storeS(0); __syncthreads();

    for (int kt = 0; kt < nk; kt++) {
        int cur = kt & 1;
        if (kt + 1 < nk) loadG((kt + 1) * BK);
        #pragma unroll
        for (int k = 0; k < BK; k++) {
            float af[TM], bf[8];
            #pragma unroll
            for (int i = 0; i < NA; i++) {
                float4 v = *reinterpret_cast<const float4*>(&As[cur][k][ty * TM + i * 4]);
                af[i * 4 + 0] = v.x; af[i * 4 + 1] = v.y;
                af[i * 4 + 2] = v.z; af[i * 4 + 3] = v.w;
            }
            {
                float4 b0 = *reinterpret_cast<const float4*>(&Bs[cur][k][tx * 8]);
                float4 b1 = *reinterpret_cast<const float4*>(&Bs[cur][k][tx * 8 + 4]);
                bf[0] = b0.x; bf[1] = b0.y; bf[2] = b0.z; bf[3] = b0.w;
                bf[4] = b1.x; bf[5] = b1.y; bf[6] = b1.z; bf[7] = b1.w;
            }
            #pragma unroll
            for (int i = 0; i < TM; i++)
                #pragma unroll
                for (int j = 0; j < 8; j++) acc[i][j] = fmaf(af[i], bf[j], acc[i][j]);
        }
        if (kt + 1 < nk) { storeS(cur ^ 1); __syncthreads(); }
    }

    // ---- epilogue: store C ----
    float4 cb0, cb1;
    if (ACT == 1) {
        cb0 = *reinterpret_cast<const float4*>(&colBias[col0 + tx * 8]);
        cb1 = *reinterpret_cast<const float4*>(&colBias[col0 + tx * 8 + 4]);
    }
    #pragma unroll
    for (int i = 0; i < TM; i++) {
        int r = row0 + ty * TM + i;
        if (r >= Mm) continue;
        float4 v0 = make_float4(acc[i][0], acc[i][1], acc[i][2], acc[i][3]);
        float4 v1 = make_float4(acc[i][4], acc[i][5], acc[i][6], acc[i][7]);
        if (ACT == 1) {
            v0.x = eluf(v0.x + cb0.x); v0.y = eluf(v0.y + cb0.y);
            v0.z = eluf(v0.z + cb0.z); v0.w = eluf(v0.w + cb0.w);
            v1.x = eluf(v1.x + cb1.x); v1.y = eluf(v1.y + cb1.y);
            v1.z = eluf(v1.z + cb1.z); v1.w = eluf(v1.w + cb1.w);
        }
        *reinterpret_cast<float4*>(&C[(long)r * ldc + col0 + tx * 8])     = v0;
        *reinterpret_cast<float4*>(&C[(long)r * ldc + col0 + tx * 8 + 4]) = v1;
    }

    // ---- fused attention dot (fc GEMM only): head = blockIdx.x, full 128-col dot ----
    if (ACT == 2) {
        float avLo[8], avHi[8];
        #pragma unroll
        for (int j = 0; j < 8; j++) {
            avLo[j] = attnLo[col0 + tx * 8 + j];
            avHi[j] = attnHi[col0 + tx * 8 + j];
        }
        int head = blockIdx.x;
        #pragma unroll
        for (int i = 0; i < TM; i++) {
            int r = row0 + ty * TM + i;
            bool lo = r < N_USER;
            float p = 0.f;
            #pragma unroll
            for (int j = 0; j < 8; j++) p += acc[i][j] * (lo ? avLo[j] : avHi[j]);
            p += __shfl_xor_sync(0xffffffffu, p, 1);
            p += __shfl_xor_sync(0xffffffffu, p, 2);
            p += __shfl_xor_sync(0xffffffffu, p, 4);
            p += __shfl_xor_sync(0xffffffffu, p, 8);
            if (tx == 0 && r < Mm) {
                if (lo) outLo[r * HH + head] = p;
                else    outHi[(r - N_USER) * HH + head] = p;
            }
        }
    }
}

// ---------------- small kernels ----------------
__global__ void zero_gat() {
    long i = (long)blockIdx.x * 256 + threadIdx.x;
    if (i < (long)N_USER * 512) g_rst[i] = 0.f;
    if (i < N_USER * HH) { g_emax[i] = INT_MIN; g_denom[i] = 0.f; }
}

__global__ void mem_init() {
    long i = (long)blockIdx.x * 256 + threadIdx.x;
    if (i < (long)NN * DD) g_agg[i] = 0.f;
    if (i < NN) g_cnt[i] = 0.f;
}

// pass 1: edge score + per-dst max (ordered-int atomicMax)
__global__ void gat_edge1(const int* __restrict__ s, const int* __restrict__ d) {
    int i = blockIdx.x * blockDim.x + threadIdx.x;
    if (i >= E_UI_C) return;
    int si = s[i], di = d[i];
    #pragma unroll
    for (int h = 0; h < HH; h++) {
        float e = lrelu(g_el[si * HH + h] + g_er[di * HH + h]);
        g_e[i * HH + h] = e;
        atomicMax(&g_emax[di * HH + h], encf(e));
    }
}

// pass 2: exp + per-dst denom
__global__ void gat_edge2(const int* __restrict__ d) {
    int i = blockIdx.x * blockDim.x + threadIdx.x;
    if (i >= E_UI_C) return;
    int di = d[i];
    #pragma unroll
    for (int h = 0; h < HH; h++) {
        float v = expf(g_e[i * HH + h] - decf(g_emax[di * HH + h]));
        g_ex[i * HH + h] = v;
        atomicAdd(&g_denom[di * HH + h], v);
    }
}

// 2 edges per 256-thread block; float4 gather of fs row + 4 scalar atomics
__global__ void gat_edge3(const int* __restrict__ s, const int* __restrict__ d,
                          const float* __restrict__ fs) {
    int sub = threadIdx.x >> 7;
    int e = blockIdx.x * 2 + sub;
    int t = threadIdx.x & 127;
    int si = s[e], di = d[e];
    int h = t >> 5;
    float a = g_ex[e * HH + h] / g_denom[di * HH + h];
    float4 f = *reinterpret_cast<const float4*>(&fs[(long)si * 512 + t * 4]);
    float* r = &g_rst[(long)di * 512 + t * 4];
    atomicAdd(r + 0, a * f.x); atomicAdd(r + 1, a * f.y);
    atomicAdd(r + 2, a * f.z); atomicAdd(r + 3, a * f.w);
}

// coef = leaky(feat[idx] . Wc[m] + bc[m]); one warp per edge/node
__global__ void coef_kernel(const float* __restrict__ feat,
                            const int* __restrict__ idx, int idxStride,
                            const float* __restrict__ Wc, int WcStride,
                            const float* __restrict__ bc, int bcStride,
                            float* __restrict__ out, int count) {
    int z = blockIdx.y;
    __shared__ float sW[MMEM * DD];
    __shared__ float sb[MMEM];
    const float* W = Wc + (long)z * WcStride;
    for (int i = threadIdx.x; i < MMEM * DD; i += 256) sW[i] = W[i];
    if (threadIdx.x < MMEM) sb[threadIdx.x] = bc[z * bcStride + threadIdx.x];
    __syncthreads();
    int warp = threadIdx.x >> 5, lane = threadIdx.x & 31;
    int e = blockIdx.x * 8 + warp;
    if (e >= count) return;
    int node = idx ? idx[(long)z * idxStride + e] : e;
    const float* f = feat + (long)node * DD;
    float fv[4];
    #pragma unroll
    for (int j = 0; j < 4; j++) fv[j] = f[lane * 4 + j];
    #pragma unroll
    for (int m = 0; m < MMEM; m++) {
        float p = 0.f;
        #pragma unroll
        for (int j = 0; j < 4; j++) p += fv[j] * sW[m * DD + lane * 4 + j];
        #pragma unroll
        for (int o = 16; o; o >>= 1) p += __shfl_xor_sync(0xffffffffu, p, o);
        if (lane == 0) out[((long)z * count + e) * MMEM + m] = lrelu(p + sb[m]);
    }
}

// warp per edge: msg = sum_m coef*tmp, scatter into agg/cnt
__global__ void rel_reduce(const int* __restrict__ edst) {
    int warp = threadIdx.x >> 5, lane = threadIdx.x & 31;
    int e = blockIdx.x * 8 + warp;
    int t = blockIdx.y;
    long ei = (long)t * E_T_C + e;
    int dd = edst[ei];
    float c = lane < MMEM ? g_coef[ei * MMEM + lane] : 0.f;
    const float* tp = g_tmp + ei * (MMEM * DD);
    float4 s = make_float4(0.f, 0.f, 0.f, 0.f);
    #pragma unroll
    for (int m = 0; m < MMEM; m++) {
        float cm = __shfl_sync(0xffffffffu, c, m);
        float4 v = *reinterpret_cast<const float4*>(&tp[m * DD + lane * 4]);
        s.x += cm * v.x; s.y += cm * v.y; s.z += cm * v.z; s.w += cm * v.w;
    }
    float* ag = &g_agg[(long)dd * DD + lane * 4];
    atomicAdd(ag + 0, s.x); atomicAdd(ag + 1, s.y);
    atomicAdd(ag + 2, s.z); atomicAdd(ag + 3, s.w);
    if (lane == 0) atomicAdd(&g_cnt[dd], 1.0f);
}

// warp per node: LN(agg/cnt)+h_bias + node-memory + leaky + trans -> next emb
__global__ void mem_finalize(const float* __restrict__ lnw, const float* __restrict__ lnb,
                             const float* __restrict__ hb, float* __restrict__ out) {
    int warp = threadIdx.x >> 5, lane = threadIdx.x & 31;
    int n = blockIdx.x * 8 + warp;
    float inv = 1.f / fmaxf(g_cnt[n], 1.f);
    float4 a = *reinterpret_cast<const float4*>(&g_agg[(long)n * DD + lane * 4]);
    a.x *= inv; a.y *= inv; a.z *= inv; a.w *= inv;
    float s = a.x + a.y + a.z + a.w;
    #pragma unroll
    for (int o = 16; o; o >>= 1) s += __shfl_xor_sync(0xffffffffu, s, o);
    float mu = s * (1.f / 128.f);
    float4 dv = make_float4(a.x - mu, a.y - mu, a.z - mu, a.w - mu);
    float vs = dv.x * dv.x + dv.y * dv.y + dv.z * dv.z + dv.w * dv.w;
    #pragma unroll
    for (int o = 16; o; o >>= 1) vs += __shfl_xor_sync(0xffffffffu, vs, o);
    float rs = rsqrtf(vs * (1.f / 128.f) + FEPS);
    float4 w4 = *reinterpret_cast<const float4*>(&lnw[lane * 4]);
    float4 b4 = *reinterpret_cast<const float4*>(&lnb[lane * 4]);
    float4 h4 = *reinterpret_cast<const float4*>(&hb[lane * 4]);
    float4 rep;
    rep.x = dv.x * rs * w4.x + b4.x + h4.x;
    rep.y = dv.y * rs * w4.y + b4.y + h4.y;
    rep.z = dv.z * rs * w4.z + b4.z + h4.z;
    rep.w = dv.w * rs * w4.w + b4.w + h4.w;
    float c = lane < MMEM ? g_ncoef[(long)n * MMEM + lane] : 0.f;
    const float* tp = g_tmp + (long)n * (MMEM * DD);
    float4 acc = make_float4(0.f, 0.f, 0.f, 0.f);
    #pragma unroll
    for (int m = 0; m < MMEM; m++) {
        float cm = __shfl_sync(0xffffffffu, c, m);
        float4 v = *reinterpret_cast<const float4*>(&tp[m * DD + lane * 4]);
        acc.x += cm * v.x; acc.y += cm * v.y; acc.z += cm * v.z; acc.w += cm * v.w;
    }
    float4 tr = *reinterpret_cast<const float4*>(&g_trans[(long)n * DD + lane * 4]);
    float4 o4;
    o4.x = lrelu(rep.x + acc.x) + tr.x;
    o4.y = lrelu(rep.y + acc.y) + tr.y;
    o4.z = lrelu(rep.z + acc.z) + tr.z;
    o4.w = lrelu(rep.w + acc.w) + tr.w;
    *reinterpret_cast<float4*>(&out[(long)n * DD + lane * 4]) = o4;
}

// warp per node: LN over concat of 3 layers (384)
__global__ void final_ln_kernel(const float* __restrict__ e0,
                                const float* __restrict__ w, const float* __restrict__ b,
                                float* __restrict__ out) {
    int warp = threadIdx.x >> 5, lane = threadIdx.x & 31;
    int n = blockIdx.x * 8 + warp;
    float4 v0 = *reinterpret_cast<const float4*>(&e0[(long)n * DD + lane * 4]);
    float4 v1 = *reinterpret_cast<const float4*>(&g_emb[(long)n * DD + lane * 4]);
    float4 v2 = *reinterpret_cast<const float4*>(&g_emb[(long)NN * DD + (long)n * DD + lane * 4]);
    float s = v0.x + v0.y + v0.z + v0.w + v1.x + v1.y + v1.z + v1.w + v2.x + v2.y + v2.z + v2.w;
    #pragma unroll
    for (int o = 16; o; o >>= 1) s += __shfl_xor_sync(0xffffffffu, s, o);
    float mu = s * (1.f / 384.f);
    float4 d0 = make_float4(v0.x - mu, v0.y - mu, v0.z - mu, v0.w - mu);
    float4 d1 = make_float4(v1.x - mu, v1.y - mu, v1.z - mu, v1.w - mu);
    float4 d2 = make_float4(v2.x - mu, v2.y - mu, v2.z - mu, v2.w - mu);
    float vs = d0.x * d0.x + d0.y * d0.y + d0.z * d0.z + d0.w * d0.w
             + d1.x * d1.x + d1.y * d1.y + d1.z * d1.z + d1.w * d1.w
             + d2.x * d2.x + d2.y * d2.y + d2.z * d2.z + d2.w * d2.w;
    #pragma unroll
    for (int o = 16; o; o >>= 1) vs += __shfl_xor_sync(0xffffffffu, vs, o);
    float r = rsqrtf(vs * (1.f / 384.f) + FEPS);
    long base = (long)n * 384;
    #pragma unroll
    for (int seg = 0; seg < 3; seg++) {
        float4 d = seg == 0 ? d0 : (seg == 1 ? d1 : d2);
        int off = seg * 128 + lane * 4;
        float4 w4 = *reinterpret_cast<const float4*>(&w[off]);
        float4 b4 = *reinterpret_cast<const float4*>(&b[off]);
        float4 o4;
        o4.x = d.x * r * w4.x + b4.x; o4.y = d.y * r * w4.y + b4.y;
        o4.z = d.z * r * w4.z + b4.z; o4.w = d.w * r * w4.w + b4.w;
        *reinterpret_cast<float4*>(&out[base + off]) = o4;
    }
}

// ---------------- host orchestration ----------------
extern "C" void kernel_launch(void* const* d_in, const int* in_sizes, int n_in,
                              void* d_out, int out_size) {
    const float* embedding   = (const float*)d_in[0];
    const float* gat_fc_W    = (const float*)d_in[1];
    const float* gat_attn_l  = (const float*)d_in[2];
    const float* gat_attn_r  = (const float*)d_in[3];
    const float* gat_bias    = (const float*)d_in[4];
    const float* proj_W      = (const float*)d_in[5];
    const float* proj_b      = (const float*)d_in[6];
    const float* mem_rel_Wc  = (const float*)d_in[7];
    const float* mem_rel_bc  = (const float*)d_in[8];
    const float* mem_rel_Ww  = (const float*)d_in[9];
    const float* mem_node_Wc = (const float*)d_in[10];
    const float* mem_node_bc = (const float*)d_in[11];
    const float* mem_node_Ww = (const float*)d_in[12];
    const float* mem_h_bias  = (const float*)d_in[13];
    const float* mem_ln_w    = (const float*)d_in[14];
    const float* mem_ln_b    = (const float*)d_in[15];
    const float* final_ln_w  = (const float*)d_in[16];
    const float* final_ln_b  = (const float*)d_in[17];
    const int*   src_u       = (const int*)d_in[18];
    const int*   dst_i       = (const int*)d_in[19];
    const int*   edge_src    = (const int*)d_in[20];
    const int*   edge_dst    = (const int*)d_in[21];

    float *emb, *fc, *rst, *trans, *el, *er, *tmp, *coefp, *ncoefp;
    cudaGetSymbolAddress((void**)&emb,    g_emb);
    cudaGetSymbolAddress((void**)&fc,     g_fc);
    cudaGetSymbolAddress((void**)&rst,    g_rst);
    cudaGetSymbolAddress((void**)&trans,  g_trans);
    cudaGetSymbolAddress((void**)&el,     g_el);
    cudaGetSymbolAddress((void**)&er,     g_er);
    cudaGetSymbolAddress((void**)&tmp,    g_tmp);
    cudaGetSymbolAddress((void**)&coefp,  g_coef);
    cudaGetSymbolAddress((void**)&ncoefp, g_ncoef);

    for (int l = 0; l < LLAYERS; l++) {
        const float* fl = (l == 0) ? embedding : (emb + (long)(l - 1) * NN * DD);
        float* flout = emb + (long)l * NN * DD;

        for (int s = 0; s < 2; s++) {
            const float* W  = gat_fc_W   + ((long)l * 2 + s) * 512 * 128;
            const float* al = gat_attn_l + ((long)l * 2 + s) * 512;
            const float* ar = gat_attn_r + ((long)l * 2 + s) * 512;
            const float* gb = gat_bias   + ((long)l * 2 + s) * 512;
            const float* pW = proj_W     + ((long)l * 2 + s) * 128 * 512;
            const float* pb = proj_b     + ((long)l * 2 + s) * 128;
            // s=0: src=items(high rows), dst=users(low); s=1: src=users(low), dst=items(high)
            const float* vecLo = (s == 0) ? ar : al;
            float*       outLo = (s == 0) ? er : el;
            const float* vecHi = (s == 0) ? al : ar;
            float*       outHi = (s == 0) ? el : er;
            const int* sidx = (s == 0) ? dst_i : src_u;
            const int* didx = (s == 0) ? src_u : dst_i;
            const float* fsp = (s == 0) ? fc + (long)N_USER * 512 : fc;

            zero_gat<<<(N_USER * 512 + 255) / 256, 256>>>();
            dim3 gfc(4, (NN + 127) / 128, 1);
            gemm_bt<8, 2, 0, 0><<<gfc, 256>>>(fl, DD, W, 0, fc, 512, 0,
                                              nullptr, nullptr,
                                              vecLo, outLo, vecHi, outHi,
                                              nullptr, 0, NN, 512, DD);
            gat_edge1<<<(E_UI_C + 255) / 256, 256>>>(sidx, didx);
            gat_edge2<<<(E_UI_C + 255) / 256, 256>>>(didx);
            gat_edge3<<<E_UI_C / 2, 256>>>(sidx, didx, fsp);
            float* Cp = trans + (long)s * N_USER * DD;
            dim3 gp(1, (N_USER + 63) / 64, 1);
            gemm_bt<4, 1, 1, 0><<<gp, 256>>>(rst, 512, pW, 0, Cp, DD, 0,
                                             pb, gb,
                                             nullptr, nullptr, nullptr, nullptr,
                                             nullptr, 0, N_USER, DD, 512);
        }

        // -------- memory layer --------
        mem_init<<<(NN * DD + 255) / 256, 256>>>();
        dim3 gc((E_T_C + 7) / 8, TREL);
        coef_kernel<<<gc, 256>>>(fl, edge_dst, E_T_C,
                                 mem_rel_Wc + (long)l * TREL * MMEM * DD, MMEM * DD,
                                 mem_rel_bc + (long)l * TREL * MMEM, MMEM,
                                 coefp, E_T_C);
        dim3 gr(8, E_T_C / 128, TREL);
        gemm_bt<8, 0, 0, 1><<<gr, 256>>>(fl, DD,
                                         mem_rel_Ww + (long)l * TREL * MMEM * DD * DD,
                                         (long)MMEM * DD * DD,
                                         tmp, MMEM * DD, (long)E_T_C * MMEM * DD,
                                         nullptr, nullptr,
                                         nullptr, nullptr, nullptr, nullptr,
                                         edge_src, E_T_C, E_T_C, MMEM * DD, DD);
        dim3 gs((E_T_C + 7) / 8, TREL);
        rel_reduce<<<gs, 256>>>(edge_dst);

        dim3 gnc((NN + 7) / 8, 1);
        coef_kernel<<<gnc, 256>>>(fl, nullptr, 0,
                                  mem_node_Wc + (long)l * MMEM * DD, 0,
                                  mem_node_bc + (long)l * MMEM, 0,
                                  ncoefp, NN);
        dim3 gn(8, (NN + 127) / 128, 1);
        gemm_bt<8, 0, 0, 0><<<gn, 256>>>(fl, DD,
                                         mem_node_Ww + (long)l * MMEM * DD * DD, 0,
                                         tmp, MMEM * DD, 0,
                                         nullptr, nullptr,
                                         nullptr, nullptr, nullptr, nullptr,
                                         nullptr, 0, NN, MMEM * DD, DD);
        mem_finalize<<<NN / 8, 256>>>(mem_ln_w + l * DD, mem_ln_b + l * DD,
                                      mem_h_bias + l * DD, flout);
    }

    final_ln_kernel<<<NN / 8, 256>>>(embedding, final_ln_w, final_ln_b, (float*)d_out);
}

// round 8
// speedup vs baseline: 1.3464x; 1.1018x over previous
#include <cuda_runtime.h>
#include <math.h>
#include <limits.h>

#define N_USER 20000
#define N_ITEM 20000
#define NN     40000
#define DD     128
#define HH     4
#define LLAYERS 2
#define MMEM   8
#define TREL   5
#define E_UI_C 40000
#define E_T_C  16000
#define FEPS   1e-5f

#define BK 16
#define LDT 132   // smem row stride (floats)

// ---------------- device scratch (no cudaMalloc allowed) ----------------
__device__ float g_emb[2L * NN * DD];                 // layers 1,2 (layer0 = input)
__device__ float g_fc[(long)NN * HH * DD];            // combined fc output (users;items)
__device__ float g_rst[(long)N_USER * HH * DD];       // GAT aggregation
__device__ float g_trans[(long)NN * DD];
__device__ float g_el[N_USER * HH];
__device__ float g_er[N_USER * HH];
__device__ int   g_emax[N_USER * HH];
__device__ float g_denom[N_USER * HH];
__device__ float g_e[E_UI_C * HH];
__device__ float g_ex[E_UI_C * HH];
__device__ float g_agg[(long)NN * DD];
__device__ float g_cnt[NN];
__device__ float g_coef[(long)TREL * E_T_C * MMEM];
__device__ float g_ncoef[(long)NN * MMEM];
__device__ float g_tmp[(long)TREL * E_T_C * MMEM * DD];   // reused for node path

// ---------------- helpers ----------------
__device__ __forceinline__ float lrelu(float x) { return x > 0.f ? x : 0.2f * x; }
__device__ __forceinline__ float eluf(float x)  { return x > 0.f ? x : expm1f(x); }
__device__ __forceinline__ int   encf(float f)  { int i = __float_as_int(f); return i >= 0 ? i : (i ^ 0x7FFFFFFF); }
__device__ __forceinline__ float decf(int i)    { return __int_as_float(i >= 0 ? i : (i ^ 0x7FFFFFFF)); }

__device__ __forceinline__ unsigned f2tf(float x) {
    unsigned u;
    asm("cvt.rna.tf32.f32 %0, %1;" : "=r"(u) : "f"(x));
    return u;
}

__device__ __forceinline__ void mma8(float* d, const unsigned* a, const unsigned* b) {
    asm("mma.sync.aligned.m16n8k8.row.col.f32.tf32.tf32.f32 "
        "{%0,%1,%2,%3}, {%4,%5,%6,%7}, {%8,%9}, {%0,%1,%2,%3};"
        : "+f"(d[0]), "+f"(d[1]), "+f"(d[2]), "+f"(d[3])
        : "r"(a[0]), "r"(a[1]), "r"(a[2]), "r"(a[3]), "r"(b[0]), "r"(b[1]));
}

// ---------------- 3xTF32 tensor-core GEMM: C = act(A[M,K] @ B[N,K]^T) ----------------
// Block tile 128x128xBK16; 8 warps = 2(m) x 4(n); warp tile 64x32 (4x4 m16n8k8 atoms).
// Each operand split into hi/lo tf32 tiles in smem; 3 MMA passes (hh, hl, lh).
// ACT: 0 plain, 1 elu(x + colBias), 2 plain store + fused attention dot (head = blockIdx.x).
// ATR: elu(a + aBias[k]) applied to A during load. GATHER: row-gather A via gidx.
template<int ACT, int ATR, int GATHER>
__global__ void __launch_bounds__(256, 2) gemm_tc(
    const float* __restrict__ A, int lda,
    const float* __restrict__ B, long strideB,
    float* __restrict__ C, int ldc, long strideC,
    const float* __restrict__ colBias,
    const float* __restrict__ aBias,
    const float* __restrict__ attnLo, float* __restrict__ outLo,
    const float* __restrict__ attnHi, float* __restrict__ outHi,
    const int* __restrict__ gidx, int strideIdx,
    int Mm, int Nn, int Kk)
{
    __shared__ float sAh[BK * LDT], sAl[BK * LDT], sBh[BK * LDT], sBl[BK * LDT];

    int z = blockIdx.z;
    B += (long)z * strideB;
    C += (long)z * strideC;
    const int* gptr = GATHER ? (gidx + (long)z * strideIdx) : nullptr;

    int tid = threadIdx.x;
    int lane = tid & 31, warp = tid >> 5;
    int warp_m = warp >> 2, warp_n = warp & 3;
    int q = lane >> 2, t4 = lane & 3;
    int row0 = blockIdx.y * 128;
    int col0 = blockIdx.x * 128;

    float acc[4][4][4];
    #pragma unroll
    for (int i = 0; i < 4; i++)
        #pragma unroll
        for (int j = 0; j < 4; j++)
            #pragma unroll
            for (int k = 0; k < 4; k++) acc[i][j][k] = 0.f;

    float4 aR[2], bR[2];

    auto loadG = [&](int k0) {
        #pragma unroll
        for (int i = 0; i < 2; i++) {
            int lin = tid + i * 256;
            int r = lin >> 2, c4 = lin & 3;
            int gr = row0 + r;
            float4 v = make_float4(0.f, 0.f, 0.f, 0.f);
            if (gr < Mm) {
                long ar = GATHER ? (long)gptr[gr] : (long)gr;
                v = *reinterpret_cast<const float4*>(&A[ar * lda + k0 + c4 * 4]);
                if (ATR) {
                    float4 b4 = *reinterpret_cast<const float4*>(&aBias[k0 + c4 * 4]);
                    v.x = eluf(v.x + b4.x); v.y = eluf(v.y + b4.y);
                    v.z = eluf(v.z + b4.z); v.w = eluf(v.w + b4.w);
                }
            }
            aR[i] = v;
        }
        #pragma unroll
        for (int i = 0; i < 2; i++) {
            int lin = tid + i * 256;
            int r = lin >> 2, c4 = lin & 3;
            bR[i] = *reinterpret_cast<const float4*>(&B[(long)(col0 + r) * Kk + k0 + c4 * 4]);
        }
    };

    auto storeS = [&]() {
        #pragma unroll
        for (int i = 0; i < 2; i++) {
            int lin = tid + i * 256;
            int r = lin >> 2, c4 = lin & 3;
            float va[4] = {aR[i].x, aR[i].y, aR[i].z, aR[i].w};
            float vb[4] = {bR[i].x, bR[i].y, bR[i].z, bR[i].w};
            #pragma unroll
            for (int j = 0; j < 4; j++) {
                int kr = c4 * 4 + j;
                float hi = __uint_as_float(f2tf(va[j]));
                sAh[kr * LDT + r] = hi;
                sAl[kr * LDT + r] = __uint_as_float(f2tf(va[j] - hi));
                float bhi = __uint_as_float(f2tf(vb[j]));
                sBh[kr * LDT + r] = bhi;
                sBl[kr * LDT + r] = __uint_as_float(f2tf(vb[j] - bhi));
            }
        }
    };

    const float* Ap[3] = {sAh, sAh, sAl};
    const float* Bp[3] = {sBh, sBl, sBh};

    int nk = Kk / BK;
    loadG(0);
    for (int kt = 0; kt < nk; kt++) {
        storeS();
        __syncthreads();
        if (kt + 1 < nk) loadG((kt + 1) * BK);
        #pragma unroll
        for (int s = 0; s < 3; s++) {
            const float* As = Ap[s];
            const float* Bs = Bp[s];
            #pragma unroll
            for (int k8 = 0; k8 < 2; k8++) {
                int kk = k8 * 8 + t4;
                unsigned af[4][4];
                #pragma unroll
                for (int ma = 0; ma < 4; ma++) {
                    int rw = warp_m * 64 + ma * 16 + q;
                    af[ma][0] = __float_as_uint(As[kk * LDT + rw]);
                    af[ma][1] = __float_as_uint(As[kk * LDT + rw + 8]);
                    af[ma][2] = __float_as_uint(As[(kk + 4) * LDT + rw]);
                    af[ma][3] = __float_as_uint(As[(kk + 4) * LDT + rw + 8]);
                }
                unsigned bf[4][2];
                #pragma unroll
                for (int na = 0; na < 4; na++) {
                    int cw = warp_n * 32 + na * 8 + q;
                    bf[na][0] = __float_as_uint(Bs[kk * LDT + cw]);
                    bf[na][1] = __float_as_uint(Bs[(kk + 4) * LDT + cw]);
                }
                #pragma unroll
                for (int ma = 0; ma < 4; ma++)
                    #pragma unroll
                    for (int na = 0; na < 4; na++) mma8(acc[ma][na], af[ma], bf[na]);
            }
        }
        __syncthreads();
    }

    // ---- epilogue: store C ----
    #pragma unroll
    for (int ma = 0; ma < 4; ma++) {
        #pragma unroll
        for (int h = 0; h < 2; h++) {
            int r = row0 + warp_m * 64 + ma * 16 + q + 8 * h;
            if (r >= Mm) continue;
            #pragma unroll
            for (int na = 0; na < 4; na++) {
                int c = col0 + warp_n * 32 + na * 8 + t4 * 2;
                float v0 = acc[ma][na][2 * h], v1 = acc[ma][na][2 * h + 1];
                if (ACT == 1) {
                    v0 = eluf(v0 + colBias[c]);
                    v1 = eluf(v1 + colBias[c + 1]);
                }
                float2 st = make_float2(v0, v1);
                *reinterpret_cast<float2*>(&C[(long)r * ldc + c]) = st;
            }
        }
    }

    // ---- fused attention dot (fc GEMM): full 128-col dot via cross-warp smem reduce ----
    if (ACT == 2) {
        float* sRed = sAh;   // 128 rows x 4 warp_n partials (smem reusable after last sync)
        #pragma unroll
        for (int ma = 0; ma < 4; ma++) {
            #pragma unroll
            for (int h = 0; h < 2; h++) {
                int rl = warp_m * 64 + ma * 16 + q + 8 * h;
                int r = row0 + rl;
                const float* av = (r < N_USER) ? attnLo : attnHi;
                float p = 0.f;
                #pragma unroll
                for (int na = 0; na < 4; na++) {
                    int c = col0 + warp_n * 32 + na * 8 + t4 * 2;
                    p += acc[ma][na][2 * h] * av[c] + acc[ma][na][2 * h + 1] * av[c + 1];
                }
                p += __shfl_xor_sync(0xffffffffu, p, 1);
                p += __shfl_xor_sync(0xffffffffu, p, 2);
                if (t4 == 0) sRed[rl * 4 + warp_n] = p;
            }
        }
        __syncthreads();
        if (tid < 128) {
            int r = row0 + tid;
            if (r < Mm) {
                float p = sRed[tid * 4] + sRed[tid * 4 + 1] + sRed[tid * 4 + 2] + sRed[tid * 4 + 3];
                int head = blockIdx.x;
                if (r < N_USER) outLo[r * HH + head] = p;
                else            outHi[(r - N_USER) * HH + head] = p;
            }
        }
    }
}

// ---------------- small kernels (unchanged, proven) ----------------
__global__ void zero_gat() {
    long i = (long)blockIdx.x * 256 + threadIdx.x;
    if (i < (long)N_USER * 512) g_rst[i] = 0.f;
    if (i < N_USER * HH) { g_emax[i] = INT_MIN; g_denom[i] = 0.f; }
}

__global__ void mem_init() {
    long i = (long)blockIdx.x * 256 + threadIdx.x;
    if (i < (long)NN * DD) g_agg[i] = 0.f;
    if (i < NN) g_cnt[i] = 0.f;
}

__global__ void gat_edge1(const int* __restrict__ s, const int* __restrict__ d) {
    int i = blockIdx.x * blockDim.x + threadIdx.x;
    if (i >= E_UI_C) return;
    int si = s[i], di = d[i];
    #pragma unroll
    for (int h = 0; h < HH; h++) {
        float e = lrelu(g_el[si * HH + h] + g_er[di * HH + h]);
        g_e[i * HH + h] = e;
        atomicMax(&g_emax[di * HH + h], encf(e));
    }
}

__global__ void gat_edge2(const int* __restrict__ d) {
    int i = blockIdx.x * blockDim.x + threadIdx.x;
    if (i >= E_UI_C) return;
    int di = d[i];
    #pragma unroll
    for (int h = 0; h < HH; h++) {
        float v = expf(g_e[i * HH + h] - decf(g_emax[di * HH + h]));
        g_ex[i * HH + h] = v;
        atomicAdd(&g_denom[di * HH + h], v);
    }
}

__global__ void gat_edge3(const int* __restrict__ s, const int* __restrict__ d,
                          const float* __restrict__ fs) {
    int sub = threadIdx.x >> 7;
    int e = blockIdx.x * 2 + sub;
    int t = threadIdx.x & 127;
    int si = s[e], di = d[e];
    int h = t >> 5;
    float a = g_ex[e * HH + h] / g_denom[di * HH + h];
    float4 f = *reinterpret_cast<const float4*>(&fs[(long)si * 512 + t * 4]);
    float* r = &g_rst[(long)di * 512 + t * 4];
    atomicAdd(r + 0, a * f.x); atomicAdd(r + 1, a * f.y);
    atomicAdd(r + 2, a * f.z); atomicAdd(r + 3, a * f.w);
}

__global__ void coef_kernel(const float* __restrict__ feat,
                            const int* __restrict__ idx, int idxStride,
                            const float* __restrict__ Wc, int WcStride,
                            const float* __restrict__ bc, int bcStride,
                            float* __restrict__ out, int count) {
    int z = blockIdx.y;
    __shared__ float sW[MMEM * DD];
    __shared__ float sb[MMEM];
    const float* W = Wc + (long)z * WcStride;
    for (int i = threadIdx.x; i < MMEM * DD; i += 256) sW[i] = W[i];
    if (threadIdx.x < MMEM) sb[threadIdx.x] = bc[z * bcStride + threadIdx.x];
    __syncthreads();
    int warp = threadIdx.x >> 5, lane = threadIdx.x & 31;
    int e = blockIdx.x * 8 + warp;
    if (e >= count) return;
    int node = idx ? idx[(long)z * idxStride + e] : e;
    const float* f = feat + (long)node * DD;
    float fv[4];
    #pragma unroll
    for (int j = 0; j < 4; j++) fv[j] = f[lane * 4 + j];
    #pragma unroll
    for (int m = 0; m < MMEM; m++) {
        float p = 0.f;
        #pragma unroll
        for (int j = 0; j < 4; j++) p += fv[j] * sW[m * DD + lane * 4 + j];
        #pragma unroll
        for (int o = 16; o; o >>= 1) p += __shfl_xor_sync(0xffffffffu, p, o);
        if (lane == 0) out[((long)z * count + e) * MMEM + m] = lrelu(p + sb[m]);
    }
}

__global__ void rel_reduce(const int* __restrict__ edst) {
    int warp = threadIdx.x >> 5, lane = threadIdx.x & 31;
    int e = blockIdx.x * 8 + warp;
    int t = blockIdx.y;
    long ei = (long)t * E_T_C + e;
    int dd = edst[ei];
    float c = lane < MMEM ? g_coef[ei * MMEM + lane] : 0.f;
    const float* tp = g_tmp + ei * (MMEM * DD);
    float4 s = make_float4(0.f, 0.f, 0.f, 0.f);
    #pragma unroll
    for (int m = 0; m < MMEM; m++) {
        float cm = __shfl_sync(0xffffffffu, c, m);
        float4 v = *reinterpret_cast<const float4*>(&tp[m * DD + lane * 4]);
        s.x += cm * v.x; s.y += cm * v.y; s.z += cm * v.z; s.w += cm * v.w;
    }
    float* ag = &g_agg[(long)dd * DD + lane * 4];
    atomicAdd(ag + 0, s.x); atomicAdd(ag + 1, s.y);
    atomicAdd(ag + 2, s.z); atomicAdd(ag + 3, s.w);
    if (lane == 0) atomicAdd(&g_cnt[dd], 1.0f);
}

__global__ void mem_finalize(const float* __restrict__ lnw, const float* __restrict__ lnb,
                             const float* __restrict__ hb, float* __restrict__ out) {
    int warp = threadIdx.x >> 5, lane = threadIdx.x & 31;
    int n = blockIdx.x * 8 + warp;
    float inv = 1.f / fmaxf(g_cnt[n], 1.f);
    float4 a = *reinterpret_cast<const float4*>(&g_agg[(long)n * DD + lane * 4]);
    a.x *= inv; a.y *= inv; a.z *= inv; a.w *= inv;
    float s = a.x + a.y + a.z + a.w;
    #pragma unroll
    for (int o = 16; o; o >>= 1) s += __shfl_xor_sync(0xffffffffu, s, o);
    float mu = s * (1.f / 128.f);
    float4 dv = make_float4(a.x - mu, a.y - mu, a.z - mu, a.w - mu);
    float vs = dv.x * dv.x + dv.y * dv.y + dv.z * dv.z + dv.w * dv.w;
    #pragma unroll
    for (int o = 16; o; o >>= 1) vs += __shfl_xor_sync(0xffffffffu, vs, o);
    float rs = rsqrtf(vs * (1.f / 128.f) + FEPS);
    float4 w4 = *reinterpret_cast<const float4*>(&lnw[lane * 4]);
    float4 b4 = *reinterpret_cast<const float4*>(&lnb[lane * 4]);
    float4 h4 = *reinterpret_cast<const float4*>(&hb[lane * 4]);
    float4 rep;
    rep.x = dv.x * rs * w4.x + b4.x + h4.x;
    rep.y = dv.y * rs * w4.y + b4.y + h4.y;
    rep.z = dv.z * rs * w4.z + b4.z + h4.z;
    rep.w = dv.w * rs * w4.w + b4.w + h4.w;
    float c = lane < MMEM ? g_ncoef[(long)n * MMEM + lane] : 0.f;
    const float* tp = g_tmp + (long)n * (MMEM * DD);
    float4 acc = make_float4(0.f, 0.f, 0.f, 0.f);
    #pragma unroll
    for (int m = 0; m < MMEM; m++) {
        float cm = __shfl_sync(0xffffffffu, c, m);
        float4 v = *reinterpret_cast<const float4*>(&tp[m * DD + lane * 4]);
        acc.x += cm * v.x; acc.y += cm * v.y; acc.z += cm * v.z; acc.w += cm * v.w;
    }
    float4 tr = *reinterpret_cast<const float4*>(&g_trans[(long)n * DD + lane * 4]);
    float4 o4;
    o4.x = lrelu(rep.x + acc.x) + tr.x;
    o4.y = lrelu(rep.y + acc.y) + tr.y;
    o4.z = lrelu(rep.z + acc.z) + tr.z;
    o4.w = lrelu(rep.w + acc.w) + tr.w;
    *reinterpret_cast<float4*>(&out[(long)n * DD + lane * 4]) = o4;
}

__global__ void final_ln_kernel(const float* __restrict__ e0,
                                const float* __restrict__ w, const float* __restrict__ b,
                                float* __restrict__ out) {
    int warp = threadIdx.x >> 5, lane = threadIdx.x & 31;
    int n = blockIdx.x * 8 + warp;
    float4 v0 = *reinterpret_cast<const float4*>(&e0[(long)n * DD + lane * 4]);
    float4 v1 = *reinterpret_cast<const float4*>(&g_emb[(long)n * DD + lane * 4]);
    float4 v2 = *reinterpret_cast<const float4*>(&g_emb[(long)NN * DD + (long)n * DD + lane * 4]);
    float s = v0.x + v0.y + v0.z + v0.w + v1.x + v1.y + v1.z + v1.w + v2.x + v2.y + v2.z + v2.w;
    #pragma unroll
    for (int o = 16; o; o >>= 1) s += __shfl_xor_sync(0xffffffffu, s, o);
    float mu = s * (1.f / 384.f);
    float4 d0 = make_float4(v0.x - mu, v0.y - mu, v0.z - mu, v0.w - mu);
    float4 d1 = make_float4(v1.x - mu, v1.y - mu, v1.z - mu, v1.w - mu);
    float4 d2 = make_float4(v2.x - mu, v2.y - mu, v2.z - mu, v2.w - mu);
    float vs = d0.x * d0.x + d0.y * d0.y + d0.z * d0.z + d0.w * d0.w
             + d1.x * d1.x + d1.y * d1.y + d1.z * d1.z + d1.w * d1.w
             + d2.x * d2.x + d2.y * d2.y + d2.z * d2.z + d2.w * d2.w;
    #pragma unroll
    for (int o = 16; o; o >>= 1) vs += __shfl_xor_sync(0xffffffffu, vs, o);
    float r = rsqrtf(vs * (1.f / 384.f) + FEPS);
    long base = (long)n * 384;
    #pragma unroll
    for (int seg = 0; seg < 3; seg++) {
        float4 d = seg == 0 ? d0 : (seg == 1 ? d1 : d2);
        int off = seg * 128 + lane * 4;
        float4 w4 = *reinterpret_cast<const float4*>(&w[off]);
        float4 b4 = *reinterpret_cast<const float4*>(&b[off]);
        float4 o4;
        o4.x = d.x * r * w4.x + b4.x; o4.y = d.y * r * w4.y + b4.y;
        o4.z = d.z * r * w4.z + b4.z; o4.w = d.w * r * w4.w + b4.w;
        *reinterpret_cast<float4*>(&out[base + off]) = o4;
    }
}

// ---------------- host orchestration ----------------
extern "C" void kernel_launch(void* const* d_in, const int* in_sizes, int n_in,
                              void* d_out, int out_size) {
    const float* embedding   = (const float*)d_in[0];
    const float* gat_fc_W    = (const float*)d_in[1];
    const float* gat_attn_l  = (const float*)d_in[2];
    const float* gat_attn_r  = (const float*)d_in[3];
    const float* gat_bias    = (const float*)d_in[4];
    const float* proj_W      = (const float*)d_in[5];
    const float* proj_b      = (const float*)d_in[6];
    const float* mem_rel_Wc  = (const float*)d_in[7];
    const float* mem_rel_bc  = (const float*)d_in[8];
    const float* mem_rel_Ww  = (const float*)d_in[9];
    const float* mem_node_Wc = (const float*)d_in[10];
    const float* mem_node_bc = (const float*)d_in[11];
    const float* mem_node_Ww = (const float*)d_in[12];
    const float* mem_h_bias  = (const float*)d_in[13];
    const float* mem_ln_w    = (const float*)d_in[14];
    const float* mem_ln_b    = (const float*)d_in[15];
    const float* final_ln_w  = (const float*)d_in[16];
    const float* final_ln_b  = (const float*)d_in[17];
    const int*   src_u       = (const int*)d_in[18];
    const int*   dst_i       = (const int*)d_in[19];
    const int*   edge_src    = (const int*)d_in[20];
    const int*   edge_dst    = (const int*)d_in[21];

    float *emb, *fc, *rst, *trans, *el, *er, *tmp, *coefp, *ncoefp;
    cudaGetSymbolAddress((void**)&emb,    g_emb);
    cudaGetSymbolAddress((void**)&fc,     g_fc);
    cudaGetSymbolAddress((void**)&rst,    g_rst);
    cudaGetSymbolAddress((void**)&trans,  g_trans);
    cudaGetSymbolAddress((void**)&el,     g_el);
    cudaGetSymbolAddress((void**)&er,     g_er);
    cudaGetSymbolAddress((void**)&tmp,    g_tmp);
    cudaGetSymbolAddress((void**)&coefp,  g_coef);
    cudaGetSymbolAddress((void**)&ncoefp, g_ncoef);

    for (int l = 0; l < LLAYERS; l++) {
        const float* fl = (l == 0) ? embedding : (emb + (long)(l - 1) * NN * DD);
        float* flout = emb + (long)l * NN * DD;

        for (int s = 0; s < 2; s++) {
            const float* W  = gat_fc_W   + ((long)l * 2 + s) * 512 * 128;
            const float* al = gat_attn_l + ((long)l * 2 + s) * 512;
            const float* ar = gat_attn_r + ((long)l * 2 + s) * 512;
            const float* gb = gat_bias   + ((long)l * 2 + s) * 512;
            const float* pW = proj_W     + ((long)l * 2 + s) * 128 * 512;
            const float* pb = proj_b     + ((long)l * 2 + s) * 128;
            // s=0: src=items(high rows), dst=users(low); s=1: src=users(low), dst=items(high)
            const float* vecLo = (s == 0) ? ar : al;
            float*       outLo = (s == 0) ? er : el;
            const float* vecHi = (s == 0) ? al : ar;
            float*       outHi = (s == 0) ? el : er;
            const int* sidx = (s == 0) ? dst_i : src_u;
            const int* didx = (s == 0) ? src_u : dst_i;
            const float* fsp = (s == 0) ? fc + (long)N_USER * 512 : fc;

            zero_gat<<<(N_USER * 512 + 255) / 256, 256>>>();
            dim3 gfc(4, (NN + 127) / 128, 1);
            gemm_tc<2, 0, 0><<<gfc, 256>>>(fl, DD, W, 0, fc, 512, 0,
                                           nullptr, nullptr,
                                           vecLo, outLo, vecHi, outHi,
                                           nullptr, 0, NN, 512, DD);
            gat_edge1<<<(E_UI_C + 255) / 256, 256>>>(sidx, didx);
            gat_edge2<<<(E_UI_C + 255) / 256, 256>>>(didx);
            gat_edge3<<<E_UI_C / 2, 256>>>(sidx, didx, fsp);
            float* Cp = trans + (long)s * N_USER * DD;
            dim3 gp(1, (N_USER + 127) / 128, 1);
            gemm_tc<1, 1, 0><<<gp, 256>>>(rst, 512, pW, 0, Cp, DD, 0,
                                          pb, gb,
                                          nullptr, nullptr, nullptr, nullptr,
                                          nullptr, 0, N_USER, DD, 512);
        }

        // -------- memory layer --------
        mem_init<<<(NN * DD + 255) / 256, 256>>>();
        dim3 gc((E_T_C + 7) / 8, TREL);
        coef_kernel<<<gc, 256>>>(fl, edge_dst, E_T_C,
                                 mem_rel_Wc + (long)l * TREL * MMEM * DD, MMEM * DD,
                                 mem_rel_bc + (long)l * TREL * MMEM, MMEM,
                                 coefp, E_T_C);
        dim3 gr(8, E_T_C / 128, TREL);
        gemm_tc<0, 0, 1><<<gr, 256>>>(fl, DD,
                                      mem_rel_Ww + (long)l * TREL * MMEM * DD * DD,
                                      (long)MMEM * DD * DD,
                                      tmp, MMEM * DD, (long)E_T_C * MMEM * DD,
                                      nullptr, nullptr,
                                      nullptr, nullptr, nullptr, nullptr,
                                      edge_src, E_T_C, E_T_C, MMEM * DD, DD);
        dim3 gs((E_T_C + 7) / 8, TREL);
        rel_reduce<<<gs, 256>>>(edge_dst);

        dim3 gnc((NN + 7) / 8, 1);
        coef_kernel<<<gnc, 256>>>(fl, nullptr, 0,
                                  mem_node_Wc + (long)l * MMEM * DD, 0,
                                  mem_node_bc + (long)l * MMEM, 0,
                                  ncoefp, NN);
        dim3 gn(8, (NN + 127) / 128, 1);
        gemm_tc<0, 0, 0><<<gn, 256>>>(fl, DD,
                                      mem_node_Ww + (long)l * MMEM * DD * DD, 0,
                                      tmp, MMEM * DD, 0,
                                      nullptr, nullptr,
                                      nullptr, nullptr, nullptr, nullptr,
                                      nullptr, 0, NN, MMEM * DD, DD);
        mem_finalize<<<NN / 8, 256>>>(mem_ln_w + l * DD, mem_ln_b + l * DD,
                                      mem_h_bias + l * DD, flout);
    }

    final_ln_kernel<<<NN / 8, 256>>>(embedding, final_ln_w, final_ln_b, (float*)d_out);
}